// round 1
// baseline (speedup 1.0000x reference)
#include <cuda_runtime.h>
#include <cuda_bf16.h>

// Problem constants (fixed by the reference).
#define BATCH   1024
#define TLEN    8192
#define NWORDS  2048
#define NTHREADS 512
#define EPT 4                      // elements per thread per iteration (float4)
#define NITERS (TLEN / (NTHREADS * EPT))   // 4

// Global accumulators: [0]=rules, [1]=pdur, [2]=wdur, [3]=sdur
__device__ double g_acc[4];

__device__ __forceinline__ void compute_gaps(int tok, float dp, float dnext, bool valid_next,
                                             float& g1, float& g2, bool& f1, bool& f2) {
    // INIT_TOKENS: 94->2, 122->3, 100->2, 92->2, 43->5, 27->5
    float ex = 0.0f;
    bool in_init = true;
    if (tok == 94 || tok == 100 || tok == 92)      ex = 2.0f;
    else if (tok == 122)                           ex = 3.0f;
    else if (tok == 43 || tok == 27)               ex = 5.0f;
    else                                           in_init = false;
    f1 = in_init && (dp > ex);
    g1 = f1 ? (dp - ex) : 0.0f;
    // RATIO_TOKENS: 44, 28, 29, 27, 121, 43
    bool in_ratio = (tok == 44) || (tok == 28) || (tok == 29) ||
                    (tok == 27) || (tok == 121) || (tok == 43);
    f2 = in_ratio && valid_next && (3.0f * dp > dnext);
    g2 = f2 ? (dp - dnext * (1.0f / 3.0f)) : 0.0f;
}

__device__ __forceinline__ float warp_sum(float v) {
#pragma unroll
    for (int o = 16; o > 0; o >>= 1) v += __shfl_down_sync(0xffffffffu, v, o);
    return v;
}

__global__ void __launch_bounds__(NTHREADS, 2) zero_acc_kernel() {
    if (threadIdx.x < 4 && blockIdx.x == 0) g_acc[threadIdx.x] = 0.0;
}

__global__ void __launch_bounds__(NTHREADS, 2) duration_loss_kernel(
    const float* __restrict__ dur_pred,
    const float* __restrict__ dur_gt,
    const int*   __restrict__ ph2word,
    const int*   __restrict__ txt_tokens)
{
    __shared__ int   s_start[NWORDS];
    __shared__ int   s_end[NWORDS];
    __shared__ float s_red[5][NTHREADS / 32];

    const int b   = blockIdx.x;
    const int tid = threadIdx.x;
    const float* dp_row = dur_pred   + (size_t)b * TLEN;
    const float* gt_row = dur_gt     + (size_t)b * TLEN;
    const int*   w_row  = ph2word    + (size_t)b * TLEN;
    const int*   t_row  = txt_tokens + (size_t)b * TLEN;

    for (int w = tid; w < NWORDS; w += NTHREADS) s_start[w] = -1;
    __syncthreads();

    float acc_rules = 0.0f, acc_pdur = 0.0f, sp = 0.0f, sg = 0.0f;

#pragma unroll
    for (int it = 0; it < NITERS; ++it) {
        const int j0 = it * (NTHREADS * EPT) + tid * EPT;

        float4 dp4 = *reinterpret_cast<const float4*>(dp_row + j0);
        float4 gt4 = *reinterpret_cast<const float4*>(gt_row + j0);
        int4   tk4 = *reinterpret_cast<const int4*>(t_row + j0);
        int4   w4  = *reinterpret_cast<const int4*>(w_row + j0);

        const bool last_chunk = (j0 + EPT >= TLEN);
        float dpn0 = 0.0f, dpn1 = 0.0f;
        int   tkn = -1, wn = -1;
        if (!last_chunk) {
            dpn0 = dp_row[j0 + 4];
            dpn1 = dp_row[j0 + 5];     // j0+5 <= TLEN-3 for non-last chunks
            tkn  = t_row[j0 + 4];
            wn   = w_row[j0 + 4];
        }
        const int wprev = (j0 > 0) ? w_row[j0 - 1] : -1;

        float dpv[6] = { dp4.x, dp4.y, dp4.z, dp4.w, dpn0, dpn1 };
        float gtv[4] = { gt4.x, gt4.y, gt4.z, gt4.w };
        int   tkv[5] = { tk4.x, tk4.y, tk4.z, tk4.w, tkn };
        int   wv[5]  = { w4.x,  w4.y,  w4.z,  w4.w,  wn  };

#pragma unroll
        for (int k = 0; k < 4; ++k) {
            const int j = j0 + k;

            // word head/tail markers (unique writer per word: ph2word is row-sorted)
            const int w      = wv[k];
            const int wprevk = (k == 0) ? wprev : wv[k - 1];
            const int wnextk = wv[k + 1];   // wv[4] = -1 on the last chunk -> tail at T-1
            if (w != wprevk) s_start[w] = j;
            if (w != wnextk) s_end[w]   = j;

            const float dpk   = dpv[k];
            const float gtk   = gtv[k];
            const float dnext = dpv[k + 1];
            const float dnn   = dpv[k + 2];
            const bool  vn    = (j < TLEN - 1);

            float g1, g2; bool f1, f2;
            compute_gaps(tkv[k], dpk, dnext, vn, g1, g2, f1, f2);
            const float selfadj = f2 ? g2 : (f1 ? g1 : 0.0f);

            float addn = 0.0f;
            if (vn) {
                float g1n, g2n; bool f1n, f2n;
                compute_gaps(tkv[k + 1], dnext, dnn, (j + 1 < TLEN - 1), g1n, g2n, f1n, f2n);
                addn = g1n + g2n;
            }
            const float rules = dpk - selfadj + addn;

            const float ldp = __logf(dpk + 1.0f);
            const float dr  = ldp - __logf(rules + 1.0f);
            acc_rules += dr * dr;
            const float dq  = ldp - __logf(gtk + 1.0f);
            acc_pdur  += dq * dq;

            sp += fmaxf(dpk, 0.0f);
            sg += gtk;
        }
    }

    __syncthreads();

    // Phase 2: per-word sums (word 0 excluded, empty words contribute 0).
    float acc_wdur = 0.0f;
    for (int w = tid; w < NWORDS; w += NTHREADS) {
        if (w == 0) continue;
        const int st = s_start[w];
        if (st < 0) continue;
        const int en = s_end[w];
        float wp = 0.0f, wg = 0.0f;
        for (int j = st; j <= en; ++j) {
            wp += fmaxf(dp_row[j], 0.0f);
            wg += gt_row[j];
        }
        const float d = __logf(wp + 1.0f) - __logf(wg + 1.0f);
        acc_wdur += d * d;
    }

    // Block reduction of 5 quantities.
    const int lane = tid & 31;
    const int wid  = tid >> 5;
    float vals[5] = { acc_rules, acc_pdur, acc_wdur, sp, sg };
#pragma unroll
    for (int q = 0; q < 5; ++q) {
        const float r = warp_sum(vals[q]);
        if (lane == 0) s_red[q][wid] = r;
    }
    __syncthreads();
    if (wid == 0) {
        float tot[5];
#pragma unroll
        for (int q = 0; q < 5; ++q) {
            float v = (lane < NTHREADS / 32) ? s_red[q][lane] : 0.0f;
            tot[q] = warp_sum(v);
        }
        if (lane == 0) {
            atomicAdd(&g_acc[0], (double)tot[0]);
            atomicAdd(&g_acc[1], (double)tot[1]);
            atomicAdd(&g_acc[2], (double)tot[2]);
            const float ds = __logf(tot[3] + 1.0f) - __logf(tot[4] + 1.0f);
            atomicAdd(&g_acc[3], (double)(ds * ds));
        }
    }
}

__global__ void finalize_kernel(float* __restrict__ out) {
    if (threadIdx.x == 0 && blockIdx.x == 0) {
        const double n_pt = (double)BATCH * (double)TLEN;            // 8388608
        const double n_w  = (double)BATCH * (double)(NWORDS - 1);    // 2096128
        const double n_s  = (double)BATCH;                           // 1024
        const double loss = 0.3 * g_acc[0] / n_pt
                          + 0.6 * g_acc[1] / n_pt
                          + 0.3 * g_acc[2] / n_w
                          + 0.1 * g_acc[3] / n_s;
        out[0] = (float)loss;
    }
}

extern "C" void kernel_launch(void* const* d_in, const int* in_sizes, int n_in,
                              void* d_out, int out_size) {
    const float* dur_pred   = (const float*)d_in[0];
    const float* dur_gt     = (const float*)d_in[1];
    const int*   ph2word    = (const int*)d_in[2];
    const int*   txt_tokens = (const int*)d_in[3];
    float* out = (float*)d_out;

    zero_acc_kernel<<<1, 32>>>();
    duration_loss_kernel<<<BATCH, NTHREADS>>>(dur_pred, dur_gt, ph2word, txt_tokens);
    finalize_kernel<<<1, 32>>>(out);
}

// round 2
// speedup vs baseline: 1.7839x; 1.7839x over previous
#include <cuda_runtime.h>

#define B_      1024
#define T_      8192
#define NW_     2048
#define NTH     512
#define NSTAGE  4
#define NCHUNK  2048          // chunks of 4 elems per row

__device__ float4       g_part[B_];
__device__ unsigned int g_count = 0;

__device__ __forceinline__ float wsumf(float v) {
#pragma unroll
    for (int o = 16; o > 0; o >>= 1) v += __shfl_down_sync(0xffffffffu, v, o);
    return v;
}
__device__ __forceinline__ double wsumd(double v) {
#pragma unroll
    for (int o = 16; o > 0; o >>= 1) v += __shfl_down_sync(0xffffffffu, v, o);
    return v;
}

__global__ void __launch_bounds__(NTH, 2) duration_loss_fused(
    const float* __restrict__ dur_pred,
    const float* __restrict__ dur_gt,
    const int*   __restrict__ ph2word,
    const int*   __restrict__ txt_tokens,
    float* __restrict__ out)
{
    __shared__ float2 s_tab[151];
    __shared__ float  s_wp[NW_], s_wg[NW_];
    __shared__ float  s_hp[NCHUNK], s_hg[NCHUNK];
    __shared__ int    s_hm[NCHUNK];
    __shared__ float  s_red[5][NTH / 32];
    __shared__ double s_dred[4][NTH / 32];
    __shared__ int    s_islast;

    const int tid  = threadIdx.x;
    const int lane = tid & 31;
    const int wid  = tid >> 5;
    const int b    = blockIdx.x;

    // token rule table: {expected_or_inf, is_ratio}
    for (int i = tid; i < 151; i += NTH) {
        float ex = 1e30f, rt = 0.0f;
        if (i == 94 || i == 100 || i == 92) ex = 2.0f;
        else if (i == 122)                  ex = 3.0f;
        else if (i == 43 || i == 27)        ex = 5.0f;
        if (i == 44 || i == 28 || i == 29 || i == 27 || i == 121 || i == 43) rt = 1.0f;
        s_tab[i] = make_float2(ex, rt);
    }
    for (int i = tid; i < NW_; i += NTH) { s_wp[i] = 0.0f; s_wg[i] = 0.0f; }
    __syncthreads();

    const float* dpr = dur_pred   + (size_t)b * T_;
    const float* gtr = dur_gt     + (size_t)b * T_;
    const int*   wr  = ph2word    + (size_t)b * T_;
    const int*   tkr = txt_tokens + (size_t)b * T_;

    float accR = 0.0f, accP = 0.0f, sp = 0.0f, sg = 0.0f;
    int   defw[NSTAGE];
    float defp[NSTAGE], defg[NSTAGE];
#pragma unroll
    for (int s = 0; s < NSTAGE; ++s) { defw[s] = -1; defp[s] = 0.0f; defg[s] = 0.0f; }

#pragma unroll
    for (int s = 0; s < NSTAGE; ++s) {
        const int j0 = s * (NTH * 4) + tid * 4;

        const float4 dp4 = *reinterpret_cast<const float4*>(dpr + j0);
        const float4 gt4 = *reinterpret_cast<const float4*>(gtr + j0);
        const int4   tk4 = *reinterpret_cast<const int4*>(tkr + j0);
        const int4   w4  = *reinterpret_cast<const int4*>(wr  + j0);

        // neighbor values: shuffle for lanes 0..30, global for warp-edge lanes
        float dpn0 = __shfl_down_sync(0xffffffffu, dp4.x, 1);
        float dpn1 = __shfl_down_sync(0xffffffffu, dp4.y, 1);
        int   tkn  = __shfl_down_sync(0xffffffffu, tk4.x, 1);
        int   wn   = __shfl_down_sync(0xffffffffu, w4.x,  1);
        int   wprev = __shfl_up_sync(0xffffffffu, w4.w, 1);
        if (lane == 31) {
            if (j0 + 4 < T_) {
                dpn0 = dpr[j0 + 4]; dpn1 = dpr[j0 + 5];
                tkn  = tkr[j0 + 4]; wn   = wr[j0 + 4];
            } else {
                dpn0 = 1e30f; dpn1 = 1e30f; tkn = 150; wn = -1;
            }
        }
        if (lane == 0) wprev = (j0 > 0) ? wr[j0 - 1] : -1;

        float dpv[6] = { dp4.x, dp4.y, dp4.z, dp4.w, dpn0, dpn1 };
        float gtv[4] = { gt4.x, gt4.y, gt4.z, gt4.w };
        int   tkv[5] = { tk4.x, tk4.y, tk4.z, tk4.w, tkn };
        int   wv[5]  = { w4.x,  w4.y,  w4.z,  w4.w,  wn  };

        // gap terms, computed once per element (elem 4 = neighbor's elem 0)
        float g[5], sa[4];
#pragma unroll
        for (int k = 0; k < 5; ++k) {
            const float2 tb = s_tab[tkv[k]];
            const float g1 = fmaxf(dpv[k] - tb.x, 0.0f);
            const float g2 = fmaxf(dpv[k] - dpv[k + 1] * (1.0f / 3.0f), 0.0f) * tb.y;
            g[k] = g1 + g2;
            if (k < 4) sa[k] = (g2 > 0.0f) ? g2 : g1;
        }

#pragma unroll
        for (int k = 0; k < 4; ++k) {
            const float rules = dpv[k] - sa[k] + g[k + 1];
            const float la = __log2f(dpv[k] + 1.0f);
            const float lr = __log2f(rules  + 1.0f);
            const float lg = __log2f(gtv[k] + 1.0f);
            const float dr = la - lr; accR = fmaf(dr, dr, accR);
            const float dq = la - lg; accP = fmaf(dq, dq, accP);
            sp += fmaxf(dpv[k], 0.0f);
            sg += gtv[k];
        }

        // ---- word-segment bookkeeping ----
        const int c = s * NTH + tid;
        float cp[4];
#pragma unroll
        for (int k = 0; k < 4; ++k) cp[k] = fmaxf(dpv[k], 0.0f);

        const bool e1 = (wv[1] == wv[0]);
        const bool e2 = e1 && (wv[2] == wv[0]);
        const bool e3 = e2 && (wv[3] == wv[0]);
        float hp = cp[0] + (e1 ? cp[1] : 0.0f) + (e2 ? cp[2] : 0.0f) + (e3 ? cp[3] : 0.0f);
        float hg = gtv[0] + (e1 ? gtv[1] : 0.0f) + (e2 ? gtv[2] : 0.0f) + (e3 ? gtv[3] : 0.0f);
        s_hp[c] = hp; s_hg[c] = hg;
        s_hm[c] = wv[0] | (e3 ? (int)0x80000000 : 0);

        // runs starting inside this chunk (unique writer per word)
        bool open = false; int rw = 0; float rp = 0.0f, rg = 0.0f;
        int pw = wprev;
#pragma unroll
        for (int k = 0; k < 4; ++k) {
            if (wv[k] != pw) {
                if (open) { s_wp[rw] = rp; s_wg[rw] = rg; }
                open = true; rw = wv[k]; rp = cp[k]; rg = gtv[k];
            } else if (open) {
                rp += cp[k]; rg += gtv[k];
            }
            pw = wv[k];
        }
        if (open) {
            if (wv[4] == rw) { defw[s] = rw; defp[s] = rp; defg[s] = rg; }
            else             { s_wp[rw] = rp; s_wg[rw] = rg; }
        }
    }
    __syncthreads();

    // resolve words spanning chunk boundaries (owner walks head-run chain)
#pragma unroll
    for (int s = 0; s < NSTAGE; ++s) {
        if (defw[s] >= 0) {
            const int w = defw[s];
            float p = defp[s], q = defg[s];
            int ci = s * NTH + tid + 1;
            while (ci < NCHUNK) {
                const int m = s_hm[ci];
                if ((m & 0x7fffffff) != w) break;
                p += s_hp[ci]; q += s_hg[ci];
                if (m >= 0) break;   // head run not full -> word ends here
                ++ci;
            }
            s_wp[w] = p; s_wg[w] = q;
        }
    }
    __syncthreads();

    // word-level loss (empty words give log2(1)-log2(1)=0, word 0 excluded)
    float accW = 0.0f;
#pragma unroll
    for (int r = 0; r < NW_ / NTH; ++r) {
        const int w = r * NTH + tid;
        if (w > 0) {
            const float d = __log2f(s_wp[w] + 1.0f) - __log2f(s_wg[w] + 1.0f);
            accW = fmaf(d, d, accW);
        }
    }

    // block reduction -> per-block partial
    float v[5] = { accR, accP, accW, sp, sg };
#pragma unroll
    for (int q = 0; q < 5; ++q) {
        const float r = wsumf(v[q]);
        if (lane == 0) s_red[q][wid] = r;
    }
    __syncthreads();
    if (wid == 0) {
        float t[5];
#pragma unroll
        for (int q = 0; q < 5; ++q) {
            float x = (lane < NTH / 32) ? s_red[q][lane] : 0.0f;
            t[q] = wsumf(x);
        }
        if (lane == 0) {
            const float ds = __log2f(t[3] + 1.0f) - __log2f(t[4] + 1.0f);
            g_part[b] = make_float4(t[0], t[1], t[2], ds * ds);
            __threadfence();
            const unsigned tk = atomicAdd(&g_count, 1u);
            s_islast = (tk == (unsigned)(gridDim.x - 1));
        }
    }
    __syncthreads();

    if (s_islast) {
        __threadfence();
        double a0 = 0.0, a1 = 0.0, a2 = 0.0, a3 = 0.0;
        for (int i = tid; i < B_; i += NTH) {
            const float4 p = g_part[i];
            a0 += p.x; a1 += p.y; a2 += p.z; a3 += p.w;
        }
        double dv[4] = { a0, a1, a2, a3 };
#pragma unroll
        for (int q = 0; q < 4; ++q) {
            const double r = wsumd(dv[q]);
            if (lane == 0) s_dred[q][wid] = r;
        }
        __syncthreads();
        if (wid == 0) {
            double t[4];
#pragma unroll
            for (int q = 0; q < 4; ++q) {
                double x = (lane < NTH / 32) ? s_dred[q][lane] : 0.0;
                t[q] = wsumd(x);
            }
            if (lane == 0) {
                const double LN2SQ = 0.4804530139182014;   // ln(2)^2
                const double loss = LN2SQ * ((0.3 * t[0] + 0.6 * t[1]) / 8388608.0
                                           + 0.3 * t[2] / 2096128.0
                                           + 0.1 * t[3] / 1024.0);
                out[0] = (float)loss;
                g_count = 0;   // reset for next graph replay
            }
        }
    }
}

extern "C" void kernel_launch(void* const* d_in, const int* in_sizes, int n_in,
                              void* d_out, int out_size) {
    const float* dur_pred   = (const float*)d_in[0];
    const float* dur_gt     = (const float*)d_in[1];
    const int*   ph2word    = (const int*)d_in[2];
    const int*   txt_tokens = (const int*)d_in[3];
    duration_loss_fused<<<B_, NTH>>>(dur_pred, dur_gt, ph2word, txt_tokens, (float*)d_out);
}